// round 16
// baseline (speedup 1.0000x reference)
#include <cuda_runtime.h>
#include <math.h>
#include <stdint.h>

typedef unsigned long long ull;

#define NB 32
#define NT 1000
#define ND 512
#define TT1 1001

// d_out layout: acoustic [32,1001,512] | token_num [32] | alphas_t [32,1001] | cif_peak [32,1001] | token_num2 [32]
#define N_AC   (NB*TT1*ND)
#define OFF_TN (N_AC)
#define OFF_AT (OFF_TN + NB)
#define OFF_CP (OFF_AT + NB*TT1)
#define OFF_TN2 (OFF_CP + NB*TT1)

// ---------------- scratch ----------------
__device__ __align__(1024) float g_y[NB*NT*ND];   // relu(conv) output
__device__ __align__(1024) float g_Wt[3*ND*ND];   // conv weights [k][i][o]
__device__ float g_v[5*ND];
__device__ float g_c2;
__device__ float g_a2sum[NB*NT];
__device__ float g_coeff[NB*TT1];
__device__ int   g_firepos[NB*TT1];
__device__ int   g_ntok[NB];

__device__ __forceinline__ void ffma2(ull &d, ull a, ull b) {
    asm("fma.rn.f32x2 %0, %1, %2, %0;" : "+l"(d) : "l"(a), "l"(b));
}
__device__ __forceinline__ ull dupf(float v) {
    ull d;
    asm("mov.b64 %0, {%1, %1};" : "=l"(d) : "f"(v));
    return d;
}
__device__ __forceinline__ uint32_t smem_u32(const void* p) {
    uint32_t a;
    asm("{ .reg .u64 t; cvta.to.shared.u64 t, %1; cvt.u32.u64 %0, t; }" : "=r"(a) : "l"(p));
    return a;
}
__device__ __forceinline__ void cp16(uint32_t dst, const void* src) {
    asm volatile("cp.async.cg.shared.global [%0], [%1], 16;" :: "r"(dst), "l"(src) : "memory");
}
__device__ __forceinline__ float sigmoidf_acc(float x) {
    if (x >= 0.f) { float z = expf(-x); return 1.f / (1.f + z); }
    float z = expf(x); return z / (1.f + z);
}
// predicated fire-position store: @(fires>=1) st.global [fp+ntok], t   (no BSSY envelope)
__device__ __forceinline__ void fire_store(float fires, int* addr, int t) {
    asm volatile("{\n\t.reg .pred p;\n\tsetp.ge.f32 p, %0, 0f3F800000;\n\t@p st.global.u32 [%1], %2;\n\t}"
        :: "f"(fires), "l"(addr), "r"(t) : "memory");
}

// ---------------- K0: unified prep (blocks 0..127 wt-transpose, 128..639 v, 640 c2) ----------------
__global__ void __launch_bounds__(256) k_prep(const float* __restrict__ cw,
                                              const float* __restrict__ uw,
                                              const float* __restrict__ w2,
                                              const float* __restrict__ ub,
                                              const float* __restrict__ b2) {
    __shared__ float sm[6144];   // 24KB
    const int blk = blockIdx.x;
    const int tid = threadIdx.x;

    if (blk < 128) {
        const int i0 = (blk >> 2) * 16;
        const int o0 = (blk & 3) * 128;
        const int ol = tid >> 1, half = tid & 1;
        const float* src = cw + ((size_t)(o0 + ol)*ND + i0)*3 + half*24;
        float4 v[6];
        #pragma unroll
        for (int q = 0; q < 6; ++q) v[q] = *(const float4*)(src + q*4);
        #pragma unroll
        for (int q = 0; q < 6; ++q) {
            float vv[4] = {v[q].x, v[q].y, v[q].z, v[q].w};
            #pragma unroll
            for (int j = 0; j < 4; ++j) {
                int e  = half*24 + q*4 + j;
                int ii = e / 3, kk = e - 3*ii;
                sm[kk*2048 + ii*128 + ol] = vv[j];
            }
        }
        __syncthreads();
        const int ol2 = tid & 127;
        for (int r = tid >> 7; r < 48; r += 2) {
            int kk = r >> 4, ii = r & 15;
            g_Wt[(size_t)kk*(ND*ND) + (size_t)(i0 + ii)*ND + o0 + ol2] = sm[kk*2048 + ii*128 + ol2];
        }
    } else if (blk < 128 + ND) {
        float* su = sm;            // [5][512]
        float* sw = sm + 2560;     // [512]
        const int i = blk - 128;
        const float* row = uw + (size_t)i * (ND*5);
        for (int q = tid; q < ND*5; q += 256) {
            int o = q / 5, j = q - 5*o;
            su[j*512 + o] = row[q];
        }
        for (int q = tid; q < ND; q += 256) sw[q] = w2[q];
        __syncthreads();
        const int j = tid >> 5, lane = tid & 31;
        if (j < 5) {
            float s = 0.f;
            for (int o = lane; o < ND; o += 32) s += su[j*512 + o] * sw[o];
            #pragma unroll
            for (int o = 16; o > 0; o >>= 1) s += __shfl_xor_sync(0xffffffffu, s, o);
            if (lane == 0) g_v[j*ND + i] = s;
        }
    } else {
        if (tid < 128) {
            const int lane = tid & 31, wid = tid >> 5;
            float s = 0.f;
            for (int o = tid; o < ND; o += 128) s += ub[o] * w2[o];
            #pragma unroll
            for (int o = 16; o > 0; o >>= 1) s += __shfl_xor_sync(0xffffffffu, s, o);
            if (lane == 0) sm[wid] = s;
        }
        __syncthreads();
        if (tid == 0) g_c2 = sm[0] + sm[1] + sm[2] + sm[3] + b2[0];
    }
}

// ---------------- K1: FFMA2 conv GEMM (R12 byte-for-byte) ----------------
#define A_BYTES 8448
#define STAGE_BYTES 33024
#define SMEM_CONV (3*STAGE_BYTES)

__global__ void __launch_bounds__(256, 2) k_conv_gemm(const float* __restrict__ enc,
                                                      const float* __restrict__ cb) {
    extern __shared__ __align__(16) char dsm[];
    const int b  = blockIdx.z;
    const int t0 = blockIdx.x * 128;
    const int o0 = blockIdx.y * 128;
    const int tid = threadIdx.x;
    const int tx = tid & 15;     // o direction
    const int ty = tid >> 4;     // t direction

    const uint32_t smem = smem_u32(dsm);

    ull acc[8][4];
    #pragma unroll
    for (int m = 0; m < 8; ++m)
        #pragma unroll
        for (int n = 0; n < 4; ++n) acc[m][n] = 0ull;

    auto ldgA = [&](int i0, float4* vbuf) {
        #pragma unroll
        for (int p = 0; p < 3; ++p) {
            int idx = tid + p*256;
            vbuf[p] = make_float4(0.f, 0.f, 0.f, 0.f);
            if (idx < 520) {
                int r = idx >> 2, c4 = idx & 3;
                int t = t0 - 1 + r;
                if (t >= 0 && t < NT)
                    vbuf[p] = *(const float4*)(enc + ((size_t)b*NT + t)*ND + i0 + c4*4);
            }
        }
    };
    auto stsA = [&](int s, const float4* vbuf) {
        float* Asp = (float*)(dsm + s*STAGE_BYTES);
        #pragma unroll
        for (int p = 0; p < 3; ++p) {
            int idx = tid + p*256;
            if (idx < 520) {
                int r = idx >> 2, c4 = idx & 3;
                float4 val = vbuf[p];
                Asp[(c4*4+0)*132 + r] = val.x;
                Asp[(c4*4+1)*132 + r] = val.y;
                Asp[(c4*4+2)*132 + r] = val.z;
                Asp[(c4*4+3)*132 + r] = val.w;
            }
        }
    };
    auto cpB = [&](int s, int i0) {
        uint32_t Bs = smem + s*STAGE_BYTES + A_BYTES;
        #pragma unroll
        for (int p = 0; p < 6; ++p) {
            int idx = tid + p*256;            // < 1536
            int kk = idx >> 9;
            int ii = (idx >> 5) & 15;
            int c4 = idx & 31;
            cp16(Bs + (uint32_t)(((kk*16 + ii)*128 + c4*4)*4),
                 g_Wt + ((size_t)kk*ND + i0 + ii)*ND + o0 + c4*4);
        }
        asm volatile("cp.async.commit_group;" ::: "memory");
    };

    float4 vbuf[3];
    ldgA(0, vbuf);  stsA(0, vbuf);  cpB(0, 0);
    ldgA(16, vbuf); stsA(1, vbuf);  cpB(1, 16);
    ldgA(32, vbuf);

    for (int c = 0; c < 32; ++c) {
        if (c < 31) asm volatile("cp.async.wait_group 1;" ::: "memory");
        else        asm volatile("cp.async.wait_group 0;" ::: "memory");
        __syncthreads();

        if (c < 30) {
            const int sw = (c + 2) % 3;
            stsA(sw, vbuf);
            cpB(sw, (c + 2) * 16);
        }
        if (c < 29) ldgA((c + 3) * 16, vbuf);

        const float* Asp = (const float*)(dsm + (c % 3)*STAGE_BYTES);
        const float* Bsf = (const float*)(dsm + (c % 3)*STAGE_BYTES + A_BYTES);
        #pragma unroll
        for (int ii = 0; ii < 16; ++ii) {
            const float4* ap = (const float4*)(Asp + ii*132 + ty*8);
            ull a[10];
            {
                float4 p0 = ap[0];
                a[0] = dupf(p0.x); a[1] = dupf(p0.y); a[2] = dupf(p0.z); a[3] = dupf(p0.w);
                float4 p1 = ap[1];
                a[4] = dupf(p1.x); a[5] = dupf(p1.y); a[6] = dupf(p1.z); a[7] = dupf(p1.w);
                float2 p2 = *(const float2*)(Asp + ii*132 + ty*8 + 8);
                a[8] = dupf(p2.x); a[9] = dupf(p2.y);
            }
            #pragma unroll
            for (int k = 0; k < 3; ++k) {
                const ulonglong2* bp = (const ulonglong2*)(Bsf + (k*16 + ii)*128 + tx*8);
                ulonglong2 b01 = bp[0];
                ulonglong2 b23 = bp[1];
                #pragma unroll
                for (int m = 0; m < 8; ++m) {
                    ffma2(acc[m][0], a[m+k], b01.x);
                    ffma2(acc[m][1], a[m+k], b01.y);
                    ffma2(acc[m][2], a[m+k], b23.x);
                    ffma2(acc[m][3], a[m+k], b23.y);
                }
            }
        }
    }

    float bias[8];
    #pragma unroll
    for (int j = 0; j < 8; ++j) bias[j] = cb[o0 + tx*8 + j];
    #pragma unroll
    for (int m = 0; m < 8; ++m) {
        int t = t0 + ty*8 + m;
        if (t < NT) {
            float outv[8];
            #pragma unroll
            for (int n = 0; n < 4; ++n) {
                float lo = __uint_as_float((unsigned)(acc[m][n] & 0xffffffffull));
                float hi = __uint_as_float((unsigned)(acc[m][n] >> 32));
                outv[2*n]   = fmaxf(lo + bias[2*n],   0.f);
                outv[2*n+1] = fmaxf(hi + bias[2*n+1], 0.f);
            }
            float4* yp = (float4*)(g_y + ((size_t)b*NT + t)*ND + o0 + tx*8);
            yp[0] = make_float4(outv[0], outv[1], outv[2], outv[3]);
            yp[1] = make_float4(outv[4], outv[5], outv[6], outv[7]);
        }
    }
}

// ---------------- K2: projections -> alphas_t[t<T], a2sum ----------------
__global__ void __launch_bounds__(256) k_proj(const float* __restrict__ mask,
        const float* __restrict__ w1, const float* __restrict__ b1,
        float* __restrict__ out_at) {
    int warp = threadIdx.x >> 5, lane = threadIdx.x & 31;
    int m = blockIdx.x * 8 + warp;
    if (m >= NB*NT) return;
    int b = m / NT, t = m - b*NT;
    const float4* yr  = (const float4*)(g_y + (size_t)m*ND);
    const float4* w1r = (const float4*)w1;
    float s[6] = {0.f,0.f,0.f,0.f,0.f,0.f};
    #pragma unroll
    for (int r = 0; r < 4; ++r) {
        int i4 = lane + 32*r;
        float4 h = yr[i4];
        float4 w = w1r[i4];
        s[0] += h.x*w.x + h.y*w.y + h.z*w.z + h.w*w.w;
        #pragma unroll
        for (int j = 0; j < 5; ++j) {
            float4 vv = *(const float4*)(g_v + j*ND + i4*4);
            s[1+j] += h.x*vv.x + h.y*vv.y + h.z*vv.z + h.w*vv.w;
        }
    }
    #pragma unroll
    for (int q = 0; q < 6; ++q)
        #pragma unroll
        for (int o = 16; o > 0; o >>= 1)
            s[q] += __shfl_xor_sync(0xffffffffu, s[q], o);
    if (lane == 0) {
        float mv = mask[b*NT + t];
        float alpha = fmaxf(sigmoidf_acc(s[0] + b1[0]), 0.f) * mv;
        float m2 = (t == 0) ? 1.f : mask[b*NT + t - 1];
        out_at[b*TT1 + t] = alpha + (m2 - mv) * 0.45f;
        float c2 = g_c2;
        float s2 = 0.f;
        #pragma unroll
        for (int j = 0; j < 5; ++j) s2 += fmaxf(sigmoidf_acc(s[1+j] + c2), 0.f);
        g_a2sum[m] = s2 * mv;
    }
}

// ---------------- K3: CIF scan — pipelined lane-0 chain (float4 prefetch, predicated STG) ----------------
__global__ void k_scan(const float* __restrict__ mask, float* __restrict__ out) {
    __shared__ __align__(16) float s_av[TT1 + 15];
    __shared__ __align__(16) float s_pk[TT1 + 15];
    __shared__ __align__(16) float s_cf[TT1 + 15];
    __shared__ int s_nt;
    int b = blockIdx.x, lane = threadIdx.x;   // 32 threads
    float* out_at = out + OFF_AT;
    float* out_cp = out + OFF_CP;

    // token_num2 (unchanged order)
    double s2 = 0.0;
    for (int t = lane; t < NT; t += 32) s2 += (double)g_a2sum[b*NT + t];
    #pragma unroll
    for (int o = 16; o > 0; o >>= 1) s2 += __shfl_xor_sync(0xffffffffu, s2, o);
    if (lane == 0) out[OFF_TN2 + b] = (float)s2;

    float tailv = mask[b*NT + NT - 1] * 0.45f;
    if (lane == 0) out_at[b*TT1 + NT] = tailv;

    // stage alphas into smem (coalesced) + token_num reduction
    double asd = 0.0;
    for (int t = lane; t < NT; t += 32) {
        float a = out_at[b*TT1 + t];
        s_av[t] = a;
        asd += (double)a;
    }
    #pragma unroll
    for (int o = 16; o > 0; o >>= 1) asd += __shfl_xor_sync(0xffffffffu, asd, o);
    asd += (double)tailv;
    if (lane == 0) {
        out[OFF_TN + b] = floorf((float)asd);
        s_av[NT] = tailv;
        s_av[NT + 1] = 0.f; s_av[NT + 2] = 0.f; s_av[NT + 3] = 0.f;  // pad block tail
    }
    __syncwarp();

    // lane 0: software-pipelined serial chain; identical float op sequence.
    if (lane == 0) {
        float integ = 0.f;
        int ntok = 0;
        int* fp = g_firepos + b*TT1;
        // 63 blocks of 16 cover 1008 >= 1001; pads are zeros (alpha=0 -> never fires,
        // but guard stores with t < TT1)
        for (int blk = 0; blk < 63; ++blk) {
            const int tb = blk * 16;
            float av[16];
            #pragma unroll
            for (int q = 0; q < 4; ++q)
                *(float4*)(av + 4*q) = *(const float4*)(s_av + tb + 4*q);
            float pk[16], cf[16];
            #pragma unroll
            for (int j = 0; j < 16; ++j) {
                float alpha = av[j];
                float dist  = 1.f - integ;
                float fires = integ + alpha;
                bool  fire  = (fires >= 1.f);
                integ = fires - (fire ? 1.0f : 0.0f);
                pk[j] = fires;
                cf[j] = fire ? dist : alpha;
                if (tb + j < TT1) {                         // compile-time except last block
                    fire_store(fires, fp + ntok, tb + j);   // @p st.global, no branch
                    ntok += fire ? 1 : 0;
                }
            }
            #pragma unroll
            for (int q = 0; q < 4; ++q) {
                *(float4*)(s_pk + tb + 4*q) = *(float4*)(pk + 4*q);
                *(float4*)(s_cf + tb + 4*q) = *(float4*)(cf + 4*q);
            }
        }
        s_nt = ntok;
    }
    __syncwarp();

    // coalesced flush
    for (int t = lane; t < TT1; t += 32) {
        out_cp[b*TT1 + t]  = s_pk[t];
        g_coeff[b*TT1 + t] = s_cf[t];
    }
    if (lane == 0) g_ntok[b] = s_nt;
}

// ---------------- K4: parallel token gather-sum ----------------
__global__ void __launch_bounds__(128) k_gather(const float* __restrict__ enc,
                                                float* __restrict__ out) {
    int b = blockIdx.y, n = blockIdx.x, tid = threadIdx.x;
    const float* at = out + OFF_AT;
    float4 acc = make_float4(0.f,0.f,0.f,0.f);
    if (n < g_ntok[b]) {
        int te = g_firepos[b*TT1 + n];
        int tstart = 0;
        if (n > 0) {
            int tp = g_firepos[b*TT1 + n - 1];
            float lw = at[b*TT1 + tp] - g_coeff[b*TT1 + tp];
            if (tp < NT) {
                float4 h = *(const float4*)(enc + ((size_t)b*NT + tp)*ND + tid*4);
                acc.x = lw*h.x; acc.y = lw*h.y; acc.z = lw*h.z; acc.w = lw*h.w;
            }
            tstart = tp + 1;
        }
        for (int t = tstart; t <= te; ++t) {
            if (t >= NT) break;
            float cf = g_coeff[b*TT1 + t];
            float4 h = *(const float4*)(enc + ((size_t)b*NT + t)*ND + tid*4);
            acc.x = fmaf(cf, h.x, acc.x);
            acc.y = fmaf(cf, h.y, acc.y);
            acc.z = fmaf(cf, h.z, acc.z);
            acc.w = fmaf(cf, h.w, acc.w);
        }
    }
    *(float4*)(out + ((size_t)(b*TT1 + n))*ND + tid*4) = acc;
}

// ---------------- launch ----------------
extern "C" void kernel_launch(void* const* d_in, const int* in_sizes, int n_in,
                              void* d_out, int out_size) {
    (void)in_sizes; (void)n_in; (void)out_size;
    const float* enc  = (const float*)d_in[0];
    const float* mask = (const float*)d_in[1];
    const float* cw   = (const float*)d_in[2];
    const float* cb   = (const float*)d_in[3];
    const float* uw   = (const float*)d_in[4];
    const float* ub   = (const float*)d_in[5];
    const float* w1   = (const float*)d_in[6];
    const float* b1   = (const float*)d_in[7];
    const float* w2   = (const float*)d_in[8];
    const float* b2   = (const float*)d_in[9];
    float* out = (float*)d_out;

    cudaFuncSetAttribute(k_conv_gemm, cudaFuncAttributeMaxDynamicSharedMemorySize, SMEM_CONV);

    k_prep<<<128 + ND + 1, 256>>>(cw, uw, w2, ub, b2);

    dim3 g1(8, 4, NB);
    k_conv_gemm<<<g1, 256, SMEM_CONV>>>(enc, cb);

    k_proj<<<(NB*NT)/8, 256>>>(mask, w1, b1, out + OFF_AT);
    k_scan<<<NB, 32>>>(mask, out);    // 4th launch -> ncu profiles the scan

    dim3 g4(TT1, NB);
    k_gather<<<g4, 128>>>(enc, out);
}

// round 17
// speedup vs baseline: 1.0283x; 1.0283x over previous
#include <cuda_runtime.h>
#include <math.h>
#include <stdint.h>

typedef unsigned long long ull;

#define NB 32
#define NT 1000
#define ND 512
#define TT1 1001

// d_out layout: acoustic [32,1001,512] | token_num [32] | alphas_t [32,1001] | cif_peak [32,1001] | token_num2 [32]
#define N_AC   (NB*TT1*ND)
#define OFF_TN (N_AC)
#define OFF_AT (OFF_TN + NB)
#define OFF_CP (OFF_AT + NB*TT1)
#define OFF_TN2 (OFF_CP + NB*TT1)

// ---------------- scratch ----------------
__device__ __align__(1024) float g_y[NB*NT*ND];   // relu(conv) output
__device__ __align__(1024) float g_Wt[3*ND*ND];   // conv weights [k][i][o]
__device__ float g_v[5*ND];
__device__ float g_c2;
__device__ float g_a2sum[NB*NT];
__device__ float g_coeff[NB*TT1];
__device__ int   g_firepos[NB*TT1];
__device__ int   g_ntok[NB];

__device__ __forceinline__ void ffma2(ull &d, ull a, ull b) {
    asm("fma.rn.f32x2 %0, %1, %2, %0;" : "+l"(d) : "l"(a), "l"(b));
}
__device__ __forceinline__ ull dupf(float v) {
    ull d;
    asm("mov.b64 %0, {%1, %1};" : "=l"(d) : "f"(v));
    return d;
}
__device__ __forceinline__ uint32_t smem_u32(const void* p) {
    uint32_t a;
    asm("{ .reg .u64 t; cvta.to.shared.u64 t, %1; cvt.u32.u64 %0, t; }" : "=r"(a) : "l"(p));
    return a;
}
__device__ __forceinline__ void cp16(uint32_t dst, const void* src) {
    asm volatile("cp.async.cg.shared.global [%0], [%1], 16;" :: "r"(dst), "l"(src) : "memory");
}
__device__ __forceinline__ float sigmoidf_acc(float x) {
    if (x >= 0.f) { float z = expf(-x); return 1.f / (1.f + z); }
    float z = expf(x); return z / (1.f + z);
}

// ---------------- K0: unified prep (blocks 0..127 wt-transpose, 128..639 v, 640 c2) ----------------
__global__ void __launch_bounds__(256) k_prep(const float* __restrict__ cw,
                                              const float* __restrict__ uw,
                                              const float* __restrict__ w2,
                                              const float* __restrict__ ub,
                                              const float* __restrict__ b2) {
    __shared__ float sm[6144];   // 24KB
    const int blk = blockIdx.x;
    const int tid = threadIdx.x;

    if (blk < 128) {
        const int i0 = (blk >> 2) * 16;
        const int o0 = (blk & 3) * 128;
        const int ol = tid >> 1, half = tid & 1;
        const float* src = cw + ((size_t)(o0 + ol)*ND + i0)*3 + half*24;
        float4 v[6];
        #pragma unroll
        for (int q = 0; q < 6; ++q) v[q] = *(const float4*)(src + q*4);
        #pragma unroll
        for (int q = 0; q < 6; ++q) {
            float vv[4] = {v[q].x, v[q].y, v[q].z, v[q].w};
            #pragma unroll
            for (int j = 0; j < 4; ++j) {
                int e  = half*24 + q*4 + j;
                int ii = e / 3, kk = e - 3*ii;
                sm[kk*2048 + ii*128 + ol] = vv[j];
            }
        }
        __syncthreads();
        const int ol2 = tid & 127;
        for (int r = tid >> 7; r < 48; r += 2) {
            int kk = r >> 4, ii = r & 15;
            g_Wt[(size_t)kk*(ND*ND) + (size_t)(i0 + ii)*ND + o0 + ol2] = sm[kk*2048 + ii*128 + ol2];
        }
    } else if (blk < 128 + ND) {
        float* su = sm;            // [5][512]
        float* sw = sm + 2560;     // [512]
        const int i = blk - 128;
        const float* row = uw + (size_t)i * (ND*5);
        for (int q = tid; q < ND*5; q += 256) {
            int o = q / 5, j = q - 5*o;
            su[j*512 + o] = row[q];
        }
        for (int q = tid; q < ND; q += 256) sw[q] = w2[q];
        __syncthreads();
        const int j = tid >> 5, lane = tid & 31;
        if (j < 5) {
            float s = 0.f;
            for (int o = lane; o < ND; o += 32) s += su[j*512 + o] * sw[o];
            #pragma unroll
            for (int o = 16; o > 0; o >>= 1) s += __shfl_xor_sync(0xffffffffu, s, o);
            if (lane == 0) g_v[j*ND + i] = s;
        }
    } else {
        if (tid < 128) {
            const int lane = tid & 31, wid = tid >> 5;
            float s = 0.f;
            for (int o = tid; o < ND; o += 128) s += ub[o] * w2[o];
            #pragma unroll
            for (int o = 16; o > 0; o >>= 1) s += __shfl_xor_sync(0xffffffffu, s, o);
            if (lane == 0) sm[wid] = s;
        }
        __syncthreads();
        if (tid == 0) g_c2 = sm[0] + sm[1] + sm[2] + sm[3] + b2[0];
    }
}

// ---------------- K1: FFMA2 conv GEMM (R12 byte-for-byte) ----------------
#define A_BYTES 8448
#define STAGE_BYTES 33024
#define SMEM_CONV (3*STAGE_BYTES)

__global__ void __launch_bounds__(256, 2) k_conv_gemm(const float* __restrict__ enc,
                                                      const float* __restrict__ cb) {
    extern __shared__ __align__(16) char dsm[];
    const int b  = blockIdx.z;
    const int t0 = blockIdx.x * 128;
    const int o0 = blockIdx.y * 128;
    const int tid = threadIdx.x;
    const int tx = tid & 15;     // o direction
    const int ty = tid >> 4;     // t direction

    const uint32_t smem = smem_u32(dsm);

    ull acc[8][4];
    #pragma unroll
    for (int m = 0; m < 8; ++m)
        #pragma unroll
        for (int n = 0; n < 4; ++n) acc[m][n] = 0ull;

    auto ldgA = [&](int i0, float4* vbuf) {
        #pragma unroll
        for (int p = 0; p < 3; ++p) {
            int idx = tid + p*256;
            vbuf[p] = make_float4(0.f, 0.f, 0.f, 0.f);
            if (idx < 520) {
                int r = idx >> 2, c4 = idx & 3;
                int t = t0 - 1 + r;
                if (t >= 0 && t < NT)
                    vbuf[p] = *(const float4*)(enc + ((size_t)b*NT + t)*ND + i0 + c4*4);
            }
        }
    };
    auto stsA = [&](int s, const float4* vbuf) {
        float* Asp = (float*)(dsm + s*STAGE_BYTES);
        #pragma unroll
        for (int p = 0; p < 3; ++p) {
            int idx = tid + p*256;
            if (idx < 520) {
                int r = idx >> 2, c4 = idx & 3;
                float4 val = vbuf[p];
                Asp[(c4*4+0)*132 + r] = val.x;
                Asp[(c4*4+1)*132 + r] = val.y;
                Asp[(c4*4+2)*132 + r] = val.z;
                Asp[(c4*4+3)*132 + r] = val.w;
            }
        }
    };
    auto cpB = [&](int s, int i0) {
        uint32_t Bs = smem + s*STAGE_BYTES + A_BYTES;
        #pragma unroll
        for (int p = 0; p < 6; ++p) {
            int idx = tid + p*256;            // < 1536
            int kk = idx >> 9;
            int ii = (idx >> 5) & 15;
            int c4 = idx & 31;
            cp16(Bs + (uint32_t)(((kk*16 + ii)*128 + c4*4)*4),
                 g_Wt + ((size_t)kk*ND + i0 + ii)*ND + o0 + c4*4);
        }
        asm volatile("cp.async.commit_group;" ::: "memory");
    };

    float4 vbuf[3];
    ldgA(0, vbuf);  stsA(0, vbuf);  cpB(0, 0);
    ldgA(16, vbuf); stsA(1, vbuf);  cpB(1, 16);
    ldgA(32, vbuf);

    for (int c = 0; c < 32; ++c) {
        if (c < 31) asm volatile("cp.async.wait_group 1;" ::: "memory");
        else        asm volatile("cp.async.wait_group 0;" ::: "memory");
        __syncthreads();

        if (c < 30) {
            const int sw = (c + 2) % 3;
            stsA(sw, vbuf);
            cpB(sw, (c + 2) * 16);
        }
        if (c < 29) ldgA((c + 3) * 16, vbuf);

        const float* Asp = (const float*)(dsm + (c % 3)*STAGE_BYTES);
        const float* Bsf = (const float*)(dsm + (c % 3)*STAGE_BYTES + A_BYTES);
        #pragma unroll
        for (int ii = 0; ii < 16; ++ii) {
            const float4* ap = (const float4*)(Asp + ii*132 + ty*8);
            ull a[10];
            {
                float4 p0 = ap[0];
                a[0] = dupf(p0.x); a[1] = dupf(p0.y); a[2] = dupf(p0.z); a[3] = dupf(p0.w);
                float4 p1 = ap[1];
                a[4] = dupf(p1.x); a[5] = dupf(p1.y); a[6] = dupf(p1.z); a[7] = dupf(p1.w);
                float2 p2 = *(const float2*)(Asp + ii*132 + ty*8 + 8);
                a[8] = dupf(p2.x); a[9] = dupf(p2.y);
            }
            #pragma unroll
            for (int k = 0; k < 3; ++k) {
                const ulonglong2* bp = (const ulonglong2*)(Bsf + (k*16 + ii)*128 + tx*8);
                ulonglong2 b01 = bp[0];
                ulonglong2 b23 = bp[1];
                #pragma unroll
                for (int m = 0; m < 8; ++m) {
                    ffma2(acc[m][0], a[m+k], b01.x);
                    ffma2(acc[m][1], a[m+k], b01.y);
                    ffma2(acc[m][2], a[m+k], b23.x);
                    ffma2(acc[m][3], a[m+k], b23.y);
                }
            }
        }
    }

    float bias[8];
    #pragma unroll
    for (int j = 0; j < 8; ++j) bias[j] = cb[o0 + tx*8 + j];
    #pragma unroll
    for (int m = 0; m < 8; ++m) {
        int t = t0 + ty*8 + m;
        if (t < NT) {
            float outv[8];
            #pragma unroll
            for (int n = 0; n < 4; ++n) {
                float lo = __uint_as_float((unsigned)(acc[m][n] & 0xffffffffull));
                float hi = __uint_as_float((unsigned)(acc[m][n] >> 32));
                outv[2*n]   = fmaxf(lo + bias[2*n],   0.f);
                outv[2*n+1] = fmaxf(hi + bias[2*n+1], 0.f);
            }
            float4* yp = (float4*)(g_y + ((size_t)b*NT + t)*ND + o0 + tx*8);
            yp[0] = make_float4(outv[0], outv[1], outv[2], outv[3]);
            yp[1] = make_float4(outv[4], outv[5], outv[6], outv[7]);
        }
    }
}

// ---------------- K2: projections -> alphas_t[t<T], a2sum ----------------
__global__ void __launch_bounds__(256) k_proj(const float* __restrict__ mask,
        const float* __restrict__ w1, const float* __restrict__ b1,
        float* __restrict__ out_at) {
    int warp = threadIdx.x >> 5, lane = threadIdx.x & 31;
    int m = blockIdx.x * 8 + warp;
    if (m >= NB*NT) return;
    int b = m / NT, t = m - b*NT;
    const float4* yr  = (const float4*)(g_y + (size_t)m*ND);
    const float4* w1r = (const float4*)w1;
    float s[6] = {0.f,0.f,0.f,0.f,0.f,0.f};
    #pragma unroll
    for (int r = 0; r < 4; ++r) {
        int i4 = lane + 32*r;
        float4 h = yr[i4];
        float4 w = w1r[i4];
        s[0] += h.x*w.x + h.y*w.y + h.z*w.z + h.w*w.w;
        #pragma unroll
        for (int j = 0; j < 5; ++j) {
            float4 vv = *(const float4*)(g_v + j*ND + i4*4);
            s[1+j] += h.x*vv.x + h.y*vv.y + h.z*vv.z + h.w*vv.w;
        }
    }
    #pragma unroll
    for (int q = 0; q < 6; ++q)
        #pragma unroll
        for (int o = 16; o > 0; o >>= 1)
            s[q] += __shfl_xor_sync(0xffffffffu, s[q], o);
    if (lane == 0) {
        float mv = mask[b*NT + t];
        float alpha = fmaxf(sigmoidf_acc(s[0] + b1[0]), 0.f) * mv;
        float m2 = (t == 0) ? 1.f : mask[b*NT + t - 1];
        out_at[b*TT1 + t] = alpha + (m2 - mv) * 0.45f;
        float c2 = g_c2;
        float s2 = 0.f;
        #pragma unroll
        for (int j = 0; j < 5; ++j) s2 += fmaxf(sigmoidf_acc(s[1+j] + c2), 0.f);
        g_a2sum[m] = s2 * mv;
    }
}

// ---------------- K3: CIF scan — register-pipelined lane-0 chain, plain branchless stores ----------------
__global__ void k_scan(const float* __restrict__ mask, float* __restrict__ out) {
    __shared__ __align__(16) float s_av[TT1 + 15];
    __shared__ __align__(16) float s_pk[TT1 + 15];
    __shared__ __align__(16) float s_cf[TT1 + 15];
    __shared__ int s_nt;
    int b = blockIdx.x, lane = threadIdx.x;   // 32 threads
    float* out_at = out + OFF_AT;
    float* out_cp = out + OFF_CP;

    // token_num2 (unchanged order)
    double s2 = 0.0;
    for (int t = lane; t < NT; t += 32) s2 += (double)g_a2sum[b*NT + t];
    #pragma unroll
    for (int o = 16; o > 0; o >>= 1) s2 += __shfl_xor_sync(0xffffffffu, s2, o);
    if (lane == 0) out[OFF_TN2 + b] = (float)s2;

    float tailv = mask[b*NT + NT - 1] * 0.45f;
    if (lane == 0) out_at[b*TT1 + NT] = tailv;

    // stage alphas into smem (coalesced) + token_num reduction
    double asd = 0.0;
    for (int t = lane; t < NT; t += 32) {
        float a = out_at[b*TT1 + t];
        s_av[t] = a;
        asd += (double)a;
    }
    #pragma unroll
    for (int o = 16; o > 0; o >>= 1) asd += __shfl_xor_sync(0xffffffffu, asd, o);
    asd += (double)tailv;
    if (lane == 0) {
        out[OFF_TN + b] = floorf((float)asd);
        s_av[NT] = tailv;
    }
    __syncwarp();

    // lane 0: register-pipelined serial chain, identical float op sequence.
    // Fire recording: unconditional slot store + predicated counter (R15 mechanism).
    if (lane == 0) {
        float integ = 0.f;
        int ntok = 0;
        int* fp = g_firepos + b*TT1;
        // 62 full blocks of 16 = steps 0..991 (guard-free)
        for (int blk = 0; blk < 62; ++blk) {
            const int tb = blk * 16;
            float av[16];
            #pragma unroll
            for (int q = 0; q < 4; ++q)
                *(float4*)(av + 4*q) = *(const float4*)(s_av + tb + 4*q);
            float pk[16], cf[16];
            #pragma unroll
            for (int j = 0; j < 16; ++j) {
                float alpha = av[j];
                float dist  = 1.f - integ;
                float fires = integ + alpha;
                bool  fire  = (fires >= 1.f);
                integ = fires - (fire ? 1.0f : 0.0f);
                pk[j] = fires;
                cf[j] = fire ? dist : alpha;
                fp[ntok] = tb + j;          // unconditional; only fires advance the slot
                ntok += fire ? 1 : 0;
            }
            #pragma unroll
            for (int q = 0; q < 4; ++q) {
                *(float4*)(s_pk + tb + 4*q) = *(float4*)(pk + 4*q);
                *(float4*)(s_cf + tb + 4*q) = *(float4*)(cf + 4*q);
            }
        }
        // scalar tail: steps 992..1000
        for (int t = 992; t < TT1; ++t) {
            float alpha = s_av[t];
            float dist  = 1.f - integ;
            float fires = integ + alpha;
            bool  fire  = (fires >= 1.f);
            integ = fires - (fire ? 1.0f : 0.0f);
            s_pk[t] = fires;
            s_cf[t] = fire ? dist : alpha;
            fp[ntok] = t;
            ntok += fire ? 1 : 0;
        }
        s_nt = ntok;
    }
    __syncwarp();

    // coalesced flush
    for (int t = lane; t < TT1; t += 32) {
        out_cp[b*TT1 + t]  = s_pk[t];
        g_coeff[b*TT1 + t] = s_cf[t];
    }
    if (lane == 0) g_ntok[b] = s_nt;
}

// ---------------- K4: parallel token gather-sum ----------------
__global__ void __launch_bounds__(128) k_gather(const float* __restrict__ enc,
                                                float* __restrict__ out) {
    int b = blockIdx.y, n = blockIdx.x, tid = threadIdx.x;
    const float* at = out + OFF_AT;
    float4 acc = make_float4(0.f,0.f,0.f,0.f);
    if (n < g_ntok[b]) {
        int te = g_firepos[b*TT1 + n];
        int tstart = 0;
        if (n > 0) {
            int tp = g_firepos[b*TT1 + n - 1];
            float lw = at[b*TT1 + tp] - g_coeff[b*TT1 + tp];
            if (tp < NT) {
                float4 h = *(const float4*)(enc + ((size_t)b*NT + tp)*ND + tid*4);
                acc.x = lw*h.x; acc.y = lw*h.y; acc.z = lw*h.z; acc.w = lw*h.w;
            }
            tstart = tp + 1;
        }
        for (int t = tstart; t <= te; ++t) {
            if (t >= NT) break;
            float cf = g_coeff[b*TT1 + t];
            float4 h = *(const float4*)(enc + ((size_t)b*NT + t)*ND + tid*4);
            acc.x = fmaf(cf, h.x, acc.x);
            acc.y = fmaf(cf, h.y, acc.y);
            acc.z = fmaf(cf, h.z, acc.z);
            acc.w = fmaf(cf, h.w, acc.w);
        }
    }
    *(float4*)(out + ((size_t)(b*TT1 + n))*ND + tid*4) = acc;
}

// ---------------- launch ----------------
extern "C" void kernel_launch(void* const* d_in, const int* in_sizes, int n_in,
                              void* d_out, int out_size) {
    (void)in_sizes; (void)n_in; (void)out_size;
    const float* enc  = (const float*)d_in[0];
    const float* mask = (const float*)d_in[1];
    const float* cw   = (const float*)d_in[2];
    const float* cb   = (const float*)d_in[3];
    const float* uw   = (const float*)d_in[4];
    const float* ub   = (const float*)d_in[5];
    const float* w1   = (const float*)d_in[6];
    const float* b1   = (const float*)d_in[7];
    const float* w2   = (const float*)d_in[8];
    const float* b2   = (const float*)d_in[9];
    float* out = (float*)d_out;

    cudaFuncSetAttribute(k_conv_gemm, cudaFuncAttributeMaxDynamicSharedMemorySize, SMEM_CONV);

    k_prep<<<128 + ND + 1, 256>>>(cw, uw, w2, ub, b2);

    dim3 g1(8, 4, NB);
    k_conv_gemm<<<g1, 256, SMEM_CONV>>>(enc, cb);

    k_proj<<<(NB*NT)/8, 256>>>(mask, w1, b1, out + OFF_AT);
    k_scan<<<NB, 32>>>(mask, out);    // 4th launch -> ncu profiles the scan

    dim3 g4(TT1, NB);
    k_gather<<<g4, 128>>>(enc, out);
}